// round 7
// baseline (speedup 1.0000x reference)
#include <cuda_runtime.h>

typedef unsigned long long ull;

#define NN 64    // nodes per graph
#define FF 64    // node feature dim
#define EE 16    // edge feature dim
#define MM 128   // message dim
#define OO 128   // output dim
#define NPASS 4
#define NTHREADS 256

// ---- packed f32x2 helpers (SASS FFMA2: 2 FMAs per instruction) ----
__device__ __forceinline__ ull dup2(float x){ ull d; asm("mov.b64 %0,{%1,%1};":"=l"(d):"f"(x)); return d; }
__device__ __forceinline__ float2 upk(ull d){ float2 f; asm("mov.b64 {%0,%1},%2;":"=f"(f.x),"=f"(f.y):"l"(d)); return f; }
__device__ __forceinline__ void fma2(ull &d, ull a, ull b){ asm("fma.rn.f32x2 %0,%1,%2,%0;":"+l"(d):"l"(a),"l"(b)); }

// ---- shared memory layout (floats) ----
#define OFF_ADJ  0          // [64][64] adjacency as float
#define OFF_H    4096       // [64][64] current hidden h
#define OFF_X    8192       // [64][64] scratch: agg_e (first 1024) / agg_h / nodes-copy
#define OFF_ME   12288      // [64][128] msg_e (pass-invariant); reused as reduce buf
#define OFF_MG   20480      // [64][128] msg (per pass)
#define OFF_MASK 28672      // [64] node mask
#define SMEM_FLOATS (28672 + 64)

__global__ __launch_bounds__(NTHREADS)
void mpnn_kernel(const int* __restrict__ adjacency,
                 const float* __restrict__ nodes,
                 const float* __restrict__ edges,
                 const float* __restrict__ W_n, const float* __restrict__ W_e,
                 const float* __restrict__ b_m,
                 const float* __restrict__ W_u, const float* __restrict__ b_u,
                 const float* __restrict__ W_r, const float* __restrict__ b_r,
                 float* __restrict__ out)
{
    extern __shared__ float sm[];
    float* sh_adj  = sm + OFF_ADJ;
    float* sh_h    = sm + OFF_H;
    float* sh_x    = sm + OFF_X;
    float* sh_me   = sm + OFF_ME;
    float* sh_mg   = sm + OFF_MG;
    float* sh_mask = sm + OFF_MASK;

    const int b   = blockIdx.x;
    const int tid = threadIdx.x;
    const int ty  = tid >> 4;     // 0..15
    const int tx  = tid & 15;     // 0..15
    const int v4  = ty * 4;       // 4 output rows per thread
    const int f0  = tx * 4;       // 4 cols (F-wide stages)
    const int m0  = tx * 8;       // 8 cols (M-wide stages)

    const int*   adjB = adjacency + b * NN * NN;
    const float* nodB = nodes + b * NN * FF;
    const float* edgB = edges + (size_t)b * NN * NN * EE;

    // ---- load adjacency (as float) and initial h = nodes ----
    #pragma unroll 4
    for (int i = tid; i < NN * NN; i += NTHREADS) sh_adj[i] = (float)adjB[i];
    #pragma unroll 4
    for (int i = tid; i < NN * FF; i += NTHREADS) sh_h[i] = nodB[i];
    __syncthreads();

    // ---- node mask: row-sum of adjacency > 0 ----
    if (tid < NN) {
        float s = 0.f;
        #pragma unroll
        for (int u = 0; u < NN; u++) s += sh_adj[tid * NN + u];
        sh_mask[tid] = (s > 0.f) ? 1.f : 0.f;
    }

    // ---- edge aggregation: agg_e[v][e] = sum_u adj[v][u] * edges[v][u][e] ----
    // adjacency is 0/1 -> predicated add, skipped loads save DRAM traffic.
    {
        const int v = tid >> 2;        // 0..63
        const int eq = tid & 3;        // 0..3  (4 floats each)
        float4 acc = make_float4(0.f, 0.f, 0.f, 0.f);
        const float* ep = edgB + (size_t)v * NN * EE + eq * 4;
        #pragma unroll 8
        for (int u = 0; u < NN; u++) {
            if (sh_adj[v * NN + u] != 0.f) {
                float4 e4 = *reinterpret_cast<const float4*>(ep + u * EE);
                acc.x += e4.x; acc.y += e4.y; acc.z += e4.z; acc.w += e4.w;
            }
        }
        *reinterpret_cast<float4*>(&sh_x[v * EE + eq * 4]) = acc;  // agg_e in sh_x[0:1024]
    }
    __syncthreads();

    // ---- msg_e = agg_e @ W_e + b_m  (pass-invariant) ----
    {
        ull acc[4][4];
        ull bm0 = *(const ull*)&b_m[m0];
        ull bm1 = *(const ull*)&b_m[m0 + 2];
        ull bm2 = *(const ull*)&b_m[m0 + 4];
        ull bm3 = *(const ull*)&b_m[m0 + 6];
        #pragma unroll
        for (int r = 0; r < 4; r++) { acc[r][0]=bm0; acc[r][1]=bm1; acc[r][2]=bm2; acc[r][3]=bm3; }
        #pragma unroll
        for (int e = 0; e < EE; e++) {
            ulonglong2 w0 = *(const ulonglong2*)&W_e[e * MM + m0];
            ulonglong2 w1 = *(const ulonglong2*)&W_e[e * MM + m0 + 4];
            #pragma unroll
            for (int r = 0; r < 4; r++) {
                ull a = dup2(sh_x[(v4 + r) * EE + e]);
                fma2(acc[r][0], a, w0.x); fma2(acc[r][1], a, w0.y);
                fma2(acc[r][2], a, w1.x); fma2(acc[r][3], a, w1.y);
            }
        }
        #pragma unroll
        for (int r = 0; r < 4; r++) {
            *(ull*)&sh_me[(v4 + r) * MM + m0]     = acc[r][0];
            *(ull*)&sh_me[(v4 + r) * MM + m0 + 2] = acc[r][1];
            *(ull*)&sh_me[(v4 + r) * MM + m0 + 4] = acc[r][2];
            *(ull*)&sh_me[(v4 + r) * MM + m0 + 6] = acc[r][3];
        }
    }
    __syncthreads();

    // ==================== message passes ====================
    for (int pass = 0; pass < NPASS; pass++) {
        // ---- stage A: agg_h = adj @ h  -> sh_x ----
        {
            ull acc[4][2] = {};
            #pragma unroll 8
            for (int u = 0; u < NN; u++) {
                ull h01 = *(const ull*)&sh_h[u * FF + f0];
                ull h23 = *(const ull*)&sh_h[u * FF + f0 + 2];
                #pragma unroll
                for (int r = 0; r < 4; r++) {
                    ull a = dup2(sh_adj[(v4 + r) * NN + u]);
                    fma2(acc[r][0], a, h01);
                    fma2(acc[r][1], a, h23);
                }
            }
            #pragma unroll
            for (int r = 0; r < 4; r++) {
                *(ull*)&sh_x[(v4 + r) * FF + f0]     = acc[r][0];
                *(ull*)&sh_x[(v4 + r) * FF + f0 + 2] = acc[r][1];
            }
        }
        __syncthreads();

        // ---- stage B: msg = agg_h @ W_n + msg_e  -> sh_mg ----
        {
            ull acc[4][4];
            #pragma unroll
            for (int r = 0; r < 4; r++) {
                acc[r][0] = *(const ull*)&sh_me[(v4 + r) * MM + m0];
                acc[r][1] = *(const ull*)&sh_me[(v4 + r) * MM + m0 + 2];
                acc[r][2] = *(const ull*)&sh_me[(v4 + r) * MM + m0 + 4];
                acc[r][3] = *(const ull*)&sh_me[(v4 + r) * MM + m0 + 6];
            }
            #pragma unroll 4
            for (int f = 0; f < FF; f++) {
                ulonglong2 w0 = *(const ulonglong2*)&W_n[f * MM + m0];
                ulonglong2 w1 = *(const ulonglong2*)&W_n[f * MM + m0 + 4];
                #pragma unroll
                for (int r = 0; r < 4; r++) {
                    ull a = dup2(sh_x[(v4 + r) * FF + f]);
                    fma2(acc[r][0], a, w0.x); fma2(acc[r][1], a, w0.y);
                    fma2(acc[r][2], a, w1.x); fma2(acc[r][3], a, w1.y);
                }
            }
            #pragma unroll
            for (int r = 0; r < 4; r++) {
                *(ull*)&sh_mg[(v4 + r) * MM + m0]     = acc[r][0];
                *(ull*)&sh_mg[(v4 + r) * MM + m0 + 2] = acc[r][1];
                *(ull*)&sh_mg[(v4 + r) * MM + m0 + 4] = acc[r][2];
                *(ull*)&sh_mg[(v4 + r) * MM + m0 + 6] = acc[r][3];
            }
        }
        __syncthreads();

        // ---- stage C: h_new = relu([h|msg] @ W_u + b_u), masked update ----
        {
            ull acc[4][2];
            ull bu0 = *(const ull*)&b_u[f0];
            ull bu1 = *(const ull*)&b_u[f0 + 2];
            #pragma unroll
            for (int r = 0; r < 4; r++) { acc[r][0] = bu0; acc[r][1] = bu1; }
            #pragma unroll 8
            for (int j = 0; j < FF; j++) {
                ulonglong2 w = *(const ulonglong2*)&W_u[j * FF + f0];
                #pragma unroll
                for (int r = 0; r < 4; r++) {
                    ull a = dup2(sh_h[(v4 + r) * FF + j]);
                    fma2(acc[r][0], a, w.x); fma2(acc[r][1], a, w.y);
                }
            }
            #pragma unroll 8
            for (int j = 0; j < MM; j++) {
                ulonglong2 w = *(const ulonglong2*)&W_u[(FF + j) * FF + f0];
                #pragma unroll
                for (int r = 0; r < 4; r++) {
                    ull a = dup2(sh_mg[(v4 + r) * MM + j]);
                    fma2(acc[r][0], a, w.x); fma2(acc[r][1], a, w.y);
                }
            }
            __syncthreads();   // all reads of sh_h done before overwrite
            #pragma unroll
            for (int r = 0; r < 4; r++) {
                int row = v4 + r;
                float mk = sh_mask[row];
                float2 p0 = upk(acc[r][0]);
                float2 p1 = upk(acc[r][1]);
                float* hp = &sh_h[row * FF + f0];
                if (mk != 0.f) {
                    hp[0] = fmaxf(p0.x, 0.f);
                    hp[1] = fmaxf(p0.y, 0.f);
                    hp[2] = fmaxf(p1.x, 0.f);
                    hp[3] = fmaxf(p1.y, 0.f);
                }
            }
            __syncthreads();
        }
    }

    // ==================== readout ====================
    // reload original nodes into sh_x
    #pragma unroll 4
    for (int i = tid; i < NN * FF; i += NTHREADS) sh_x[i] = nodB[i];
    __syncthreads();

    {
        ull acc[4][4];
        ull br0 = *(const ull*)&b_r[m0];
        ull br1 = *(const ull*)&b_r[m0 + 2];
        ull br2 = *(const ull*)&b_r[m0 + 4];
        ull br3 = *(const ull*)&b_r[m0 + 6];
        #pragma unroll
        for (int r = 0; r < 4; r++) { acc[r][0]=br0; acc[r][1]=br1; acc[r][2]=br2; acc[r][3]=br3; }

        #pragma unroll 4
        for (int j = 0; j < FF; j++) {          // h part
            ulonglong2 w0 = *(const ulonglong2*)&W_r[j * OO + m0];
            ulonglong2 w1 = *(const ulonglong2*)&W_r[j * OO + m0 + 4];
            #pragma unroll
            for (int r = 0; r < 4; r++) {
                ull a = dup2(sh_h[(v4 + r) * FF + j]);
                fma2(acc[r][0], a, w0.x); fma2(acc[r][1], a, w0.y);
                fma2(acc[r][2], a, w1.x); fma2(acc[r][3], a, w1.y);
            }
        }
        #pragma unroll 4
        for (int j = 0; j < FF; j++) {          // nodes part
            ulonglong2 w0 = *(const ulonglong2*)&W_r[(FF + j) * OO + m0];
            ulonglong2 w1 = *(const ulonglong2*)&W_r[(FF + j) * OO + m0 + 4];
            #pragma unroll
            for (int r = 0; r < 4; r++) {
                ull a = dup2(sh_x[(v4 + r) * FF + j]);
                fma2(acc[r][0], a, w0.x); fma2(acc[r][1], a, w0.y);
                fma2(acc[r][2], a, w1.x); fma2(acc[r][3], a, w1.y);
            }
        }

        // relu + mask + partial row-sum over this thread's 4 rows
        float prt[8] = {0,0,0,0,0,0,0,0};
        #pragma unroll
        for (int r = 0; r < 4; r++) {
            float mk = sh_mask[v4 + r];
            #pragma unroll
            for (int k = 0; k < 4; k++) {
                float2 p = upk(acc[r][k]);
                prt[2*k]   += mk * fmaxf(p.x, 0.f);
                prt[2*k+1] += mk * fmaxf(p.y, 0.f);
            }
        }
        // reduce across the 16 ty groups via sh_me (dead now)
        #pragma unroll
        for (int c = 0; c < 8; c++) sh_me[ty * MM + m0 + c] = prt[c];
    }
    __syncthreads();

    if (tid < OO) {
        float s = 0.f;
        #pragma unroll
        for (int t = 0; t < 16; t++) s += sh_me[t * MM + tid];
        out[(size_t)b * OO + tid] = s;
    }
}

extern "C" void kernel_launch(void* const* d_in, const int* in_sizes, int n_in,
                              void* d_out, int out_size)
{
    const int*   adjacency = (const int*)  d_in[0];
    const float* nodes     = (const float*)d_in[1];
    const float* edges     = (const float*)d_in[2];
    const float* W_n       = (const float*)d_in[3];
    const float* W_e       = (const float*)d_in[4];
    const float* b_m       = (const float*)d_in[5];
    const float* W_u       = (const float*)d_in[6];
    const float* b_u       = (const float*)d_in[7];
    const float* W_r       = (const float*)d_in[8];
    const float* b_r       = (const float*)d_in[9];
    float* out = (float*)d_out;

    const int B = in_sizes[0] / (NN * NN);
    const int smem_bytes = SMEM_FLOATS * (int)sizeof(float);
    cudaFuncSetAttribute(mpnn_kernel, cudaFuncAttributeMaxDynamicSharedMemorySize, smem_bytes);
    mpnn_kernel<<<B, NTHREADS, smem_bytes>>>(adjacency, nodes, edges,
                                             W_n, W_e, b_m, W_u, b_u, W_r, b_r, out);
}

// round 15
// speedup vs baseline: 1.7414x; 1.7414x over previous
#include <cuda_runtime.h>

typedef unsigned long long ull;

#define NN 64    // nodes per graph
#define FF 64    // node feature dim
#define EE 16    // edge feature dim
#define MM 128   // message dim
#define OO 128   // output dim
#define NPASS 4
#define NTHREADS 256

// ---- packed f32x2 helpers (SASS FFMA2) ----
__device__ __forceinline__ ull dup2(float x){ ull d; asm("mov.b64 %0,{%1,%1};":"=l"(d):"f"(x)); return d; }
__device__ __forceinline__ float2 upk(ull d){ float2 f; asm("mov.b64 {%0,%1},%2;":"=f"(f.x),"=f"(f.y):"l"(d)); return f; }
__device__ __forceinline__ void fma2(ull &d, ull a, ull b){ asm("fma.rn.f32x2 %0,%1,%2,%0;":"+l"(d):"l"(a),"l"(b)); }

// ---- precomputed folded weights (written by prep_kernel) ----
__device__ __align__(16) float g_Wnu[FF * FF];   // W_n @ W_u2   [64][64]
__device__ __align__(16) float g_Weu[EE * FF];   // W_e @ W_u2   [16][64]
__device__ __align__(16) float g_b2[FF];         // b_m @ W_u2 + b_u

// ============ prep: fold W_n/W_e/b_m through W_u2 (once, tiny) ============
__global__ void prep_kernel(const float* __restrict__ W_n, const float* __restrict__ W_e,
                            const float* __restrict__ b_m, const float* __restrict__ W_u,
                            const float* __restrict__ b_u)
{
    const int tid = threadIdx.x;
    const int ty = tid >> 4, tx = tid & 15;
    const int o0 = tx * 4;

    // W_nu[f][o] = sum_k W_n[f][k] * W_u[64+k][o]   (4 rows per thread)
    float4 acc[4] = {};
    for (int k = 0; k < MM; k++) {
        float4 w = *(const float4*)&W_u[(FF + k) * FF + o0];
        #pragma unroll
        for (int r = 0; r < 4; r++) {
            float a = W_n[(ty * 4 + r) * MM + k];
            acc[r].x += a * w.x; acc[r].y += a * w.y;
            acc[r].z += a * w.z; acc[r].w += a * w.w;
        }
    }
    #pragma unroll
    for (int r = 0; r < 4; r++)
        *(float4*)&g_Wnu[(ty * 4 + r) * FF + o0] = acc[r];

    // W_eu[e][o] = sum_k W_e[e][k] * W_u[64+k][o]   (row e = ty, 0..15)
    float4 ae = make_float4(0.f, 0.f, 0.f, 0.f);
    for (int k = 0; k < MM; k++) {
        float4 w = *(const float4*)&W_u[(FF + k) * FF + o0];
        float a = W_e[ty * MM + k];
        ae.x += a * w.x; ae.y += a * w.y; ae.z += a * w.z; ae.w += a * w.w;
    }
    *(float4*)&g_Weu[ty * FF + o0] = ae;

    // b2[o] = sum_k b_m[k] * W_u[64+k][o] + b_u[o]
    if (tid < FF) {
        float s = b_u[tid];
        for (int k = 0; k < MM; k++) s += b_m[k] * W_u[(FF + k) * FF + tid];
        g_b2[tid] = s;
    }
}

// ---- shared memory layout (floats) ----
#define OFF_ADJ  0          // [64][64] adjacency as float
#define OFF_H    4096       // [64][64] current hidden h
#define OFF_X    8192       // scratch: agg_e [64][16] / agg_h [64][64] / nodes copy
#define OFF_E2   12288      // [64][64] pass-invariant edge term; reduce buf at readout
#define OFF_MASK 16384      // [64] node mask
#define SMEM_FLOATS (16384 + 64)

__global__ __launch_bounds__(NTHREADS, 3)
void mpnn_kernel(const int* __restrict__ adjacency,
                 const float* __restrict__ nodes,
                 const float* __restrict__ edges,
                 const float* __restrict__ W_u,
                 const float* __restrict__ W_r, const float* __restrict__ b_r,
                 float* __restrict__ out)
{
    extern __shared__ float sm[];
    float* sh_adj  = sm + OFF_ADJ;
    float* sh_h    = sm + OFF_H;
    float* sh_x    = sm + OFF_X;
    float* sh_e2   = sm + OFF_E2;
    float* sh_mask = sm + OFF_MASK;

    const int b   = blockIdx.x;
    const int tid = threadIdx.x;
    const int ty  = tid >> 4;     // 0..15
    const int tx  = tid & 15;     // 0..15
    const int v4  = ty * 4;       // 4 output rows per thread
    const int f0  = tx * 4;       // 4 cols (F-wide stages)
    const int m0  = tx * 8;       // 8 cols (readout)

    const int*   adjB = adjacency + b * NN * NN;
    const float* nodB = nodes + b * NN * FF;
    const float* edgB = edges + (size_t)b * NN * NN * EE;

    // ---- load adjacency (as float) and initial h = nodes ----
    #pragma unroll 4
    for (int i = tid; i < NN * NN; i += NTHREADS) sh_adj[i] = (float)adjB[i];
    #pragma unroll 4
    for (int i = tid; i < NN * FF; i += NTHREADS) sh_h[i] = nodB[i];
    __syncthreads();

    // ---- node mask ----
    if (tid < NN) {
        float s = 0.f;
        #pragma unroll
        for (int u = 0; u < NN; u++) s += sh_adj[tid * NN + u];
        sh_mask[tid] = (s > 0.f) ? 1.f : 0.f;
    }

    // ---- edge aggregation: agg_e[v][e] -> sh_x[64][16] ----
    {
        const int v  = tid >> 2;
        const int eq = tid & 3;
        float4 acc = make_float4(0.f, 0.f, 0.f, 0.f);
        const float* ep = edgB + (size_t)v * NN * EE + eq * 4;
        #pragma unroll 8
        for (int u = 0; u < NN; u++) {
            if (sh_adj[v * NN + u] != 0.f) {
                float4 e4 = *reinterpret_cast<const float4*>(ep + u * EE);
                acc.x += e4.x; acc.y += e4.y; acc.z += e4.z; acc.w += e4.w;
            }
        }
        *reinterpret_cast<float4*>(&sh_x[v * EE + eq * 4]) = acc;
    }
    __syncthreads();

    // ---- E2 = agg_e @ W_eu + b2  (pass-invariant, [64][64]) ----
    {
        float4 bb = *(const float4*)&g_b2[f0];
        float4 acc[4];
        #pragma unroll
        for (int r = 0; r < 4; r++) acc[r] = bb;
        #pragma unroll
        for (int e = 0; e < EE; e++) {
            float4 w = *(const float4*)&g_Weu[e * FF + f0];
            #pragma unroll
            for (int r = 0; r < 4; r++) {
                float a = sh_x[(v4 + r) * EE + e];
                acc[r].x += a * w.x; acc[r].y += a * w.y;
                acc[r].z += a * w.z; acc[r].w += a * w.w;
            }
        }
        #pragma unroll
        for (int r = 0; r < 4; r++)
            *(float4*)&sh_e2[(v4 + r) * FF + f0] = acc[r];
    }
    __syncthreads();

    // ==================== message passes ====================
    for (int pass = 0; pass < NPASS; pass++) {
        // ---- A: agg_h = adj @ h  -> sh_x[64][64] ----
        {
            ull acc[4][2] = {};
            #pragma unroll 8
            for (int u = 0; u < NN; u++) {
                ull h01 = *(const ull*)&sh_h[u * FF + f0];
                ull h23 = *(const ull*)&sh_h[u * FF + f0 + 2];
                #pragma unroll
                for (int r = 0; r < 4; r++) {
                    ull a = dup2(sh_adj[(v4 + r) * NN + u]);
                    fma2(acc[r][0], a, h01);
                    fma2(acc[r][1], a, h23);
                }
            }
            #pragma unroll
            for (int r = 0; r < 4; r++) {
                *(ull*)&sh_x[(v4 + r) * FF + f0]     = acc[r][0];
                *(ull*)&sh_x[(v4 + r) * FF + f0 + 2] = acc[r][1];
            }
        }
        __syncthreads();

        // ---- B': pre = h @ W_u1 + agg_h @ W_nu + E2 ; h = relu(pre) masked ----
        {
            ull acc[4][2];
            #pragma unroll
            for (int r = 0; r < 4; r++) {
                acc[r][0] = *(const ull*)&sh_e2[(v4 + r) * FF + f0];
                acc[r][1] = *(const ull*)&sh_e2[(v4 + r) * FF + f0 + 2];
            }
            #pragma unroll 4
            for (int j = 0; j < FF; j++) {
                ulonglong2 wu = *(const ulonglong2*)&W_u[j * FF + f0];     // W_u1 row j
                ulonglong2 wn = *(const ulonglong2*)&g_Wnu[j * FF + f0];   // W_nu row j
                #pragma unroll
                for (int r = 0; r < 4; r++) {
                    ull ah = dup2(sh_h[(v4 + r) * FF + j]);
                    ull ag = dup2(sh_x[(v4 + r) * FF + j]);
                    fma2(acc[r][0], ah, wu.x); fma2(acc[r][1], ah, wu.y);
                    fma2(acc[r][0], ag, wn.x); fma2(acc[r][1], ag, wn.y);
                }
            }
            __syncthreads();   // all reads of sh_h / sh_x done before overwrite
            #pragma unroll
            for (int r = 0; r < 4; r++) {
                int row = v4 + r;
                if (sh_mask[row] != 0.f) {
                    float2 p0 = upk(acc[r][0]);
                    float2 p1 = upk(acc[r][1]);
                    float* hp = &sh_h[row * FF + f0];
                    hp[0] = fmaxf(p0.x, 0.f);
                    hp[1] = fmaxf(p0.y, 0.f);
                    hp[2] = fmaxf(p1.x, 0.f);
                    hp[3] = fmaxf(p1.y, 0.f);
                }
            }
            __syncthreads();
        }
    }

    // ==================== readout ====================
    #pragma unroll 4
    for (int i = tid; i < NN * FF; i += NTHREADS) sh_x[i] = nodB[i];
    __syncthreads();

    {
        ull acc[4][4];
        ull br0 = *(const ull*)&b_r[m0];
        ull br1 = *(const ull*)&b_r[m0 + 2];
        ull br2 = *(const ull*)&b_r[m0 + 4];
        ull br3 = *(const ull*)&b_r[m0 + 6];
        #pragma unroll
        for (int r = 0; r < 4; r++) { acc[r][0]=br0; acc[r][1]=br1; acc[r][2]=br2; acc[r][3]=br3; }

        #pragma unroll 4
        for (int j = 0; j < FF; j++) {          // h part
            ulonglong2 w0 = *(const ulonglong2*)&W_r[j * OO + m0];
            ulonglong2 w1 = *(const ulonglong2*)&W_r[j * OO + m0 + 4];
            #pragma unroll
            for (int r = 0; r < 4; r++) {
                ull a = dup2(sh_h[(v4 + r) * FF + j]);
                fma2(acc[r][0], a, w0.x); fma2(acc[r][1], a, w0.y);
                fma2(acc[r][2], a, w1.x); fma2(acc[r][3], a, w1.y);
            }
        }
        #pragma unroll 4
        for (int j = 0; j < FF; j++) {          // nodes part
            ulonglong2 w0 = *(const ulonglong2*)&W_r[(FF + j) * OO + m0];
            ulonglong2 w1 = *(const ulonglong2*)&W_r[(FF + j) * OO + m0 + 4];
            #pragma unroll
            for (int r = 0; r < 4; r++) {
                ull a = dup2(sh_x[(v4 + r) * FF + j]);
                fma2(acc[r][0], a, w0.x); fma2(acc[r][1], a, w0.y);
                fma2(acc[r][2], a, w1.x); fma2(acc[r][3], a, w1.y);
            }
        }

        // relu + mask + partial row-sum over this thread's 4 rows
        float prt[8] = {0,0,0,0,0,0,0,0};
        #pragma unroll
        for (int r = 0; r < 4; r++) {
            float mk = sh_mask[v4 + r];
            #pragma unroll
            for (int k = 0; k < 4; k++) {
                float2 p = upk(acc[r][k]);
                prt[2*k]   += mk * fmaxf(p.x, 0.f);
                prt[2*k+1] += mk * fmaxf(p.y, 0.f);
            }
        }
        #pragma unroll
        for (int c = 0; c < 8; c++) sh_e2[ty * OO + m0 + c] = prt[c];  // E2 dead: reduce buf
    }
    __syncthreads();

    if (tid < OO) {
        float s = 0.f;
        #pragma unroll
        for (int t = 0; t < 16; t++) s += sh_e2[t * OO + tid];
        out[(size_t)b * OO + tid] = s;
    }
}

extern "C" void kernel_launch(void* const* d_in, const int* in_sizes, int n_in,
                              void* d_out, int out_size)
{
    const int*   adjacency = (const int*)  d_in[0];
    const float* nodes     = (const float*)d_in[1];
    const float* edges     = (const float*)d_in[2];
    const float* W_n       = (const float*)d_in[3];
    const float* W_e       = (const float*)d_in[4];
    const float* b_m       = (const float*)d_in[5];
    const float* W_u       = (const float*)d_in[6];
    const float* b_u       = (const float*)d_in[7];
    const float* W_r       = (const float*)d_in[8];
    const float* b_r       = (const float*)d_in[9];
    float* out = (float*)d_out;

    const int B = in_sizes[0] / (NN * NN);
    const int smem_bytes = SMEM_FLOATS * (int)sizeof(float);

    prep_kernel<<<1, NTHREADS>>>(W_n, W_e, b_m, W_u, b_u);

    cudaFuncSetAttribute(mpnn_kernel, cudaFuncAttributeMaxDynamicSharedMemorySize, smem_bytes);
    mpnn_kernel<<<B, NTHREADS, smem_bytes>>>(adjacency, nodes, edges,
                                             W_u, W_r, b_r, out);
}